// round 7
// baseline (speedup 1.0000x reference)
#include <cuda_runtime.h>
#include <math.h>
#include <stdint.h>

// ---------------- device scratch ----------------
__device__ float g_xp[(size_t)2 * 512 * 1024 * 64];   // [dir][t][gate_row 0..1023][b]
__device__ float g_hP[(size_t)512 * 2 * 64 * 64 * 4]; // [t][d][jq][b][4]  (64MB)
__device__ float g_emis[(size_t)512 * 64 * 9];        // [t][b][tau]
__device__ float g_llh[64];
__device__ int   g_cnt[1024];                         // sub-counters: [d*512 + sub*32]

// ---------------- packed f32x2 helpers (Blackwell FFMA2) ----------------
__device__ __forceinline__ unsigned long long ffma2(unsigned long long a,
                                                    unsigned long long b,
                                                    unsigned long long c) {
    unsigned long long d;
    asm("fma.rn.f32x2 %0, %1, %2, %3;" : "=l"(d) : "l"(a), "l"(b), "l"(c));
    return d;
}
__device__ __forceinline__ float hsum2(unsigned long long v) {
    float lo, hi;
    asm("mov.b64 {%0, %1}, %2;" : "=f"(lo), "=f"(hi) : "l"(v));
    return lo + hi;
}
__device__ __forceinline__ float tanh_ap(float x) {
    float y;
    asm("tanh.approx.f32 %0, %1;" : "=f"(y) : "f"(x));
    return y;
}
__device__ __forceinline__ float sig_ap(float x) {
    return 0.5f * tanh_ap(0.5f * x) + 0.5f;
}

// ---------------- profiling-slot shifters (no-op) ----------------
__global__ void k_pre1() {}
__global__ void k_pre2() {}

// ===========================================================================
// K1: fused embedding gather + input projection GEMM (+ bih+bhh bias)
// ===========================================================================
__global__ void __launch_bounds__(256) k_inproj(
    const int*   __restrict__ sent,
    const float* __restrict__ embed,
    const float* __restrict__ wih_f, const float* __restrict__ wih_b,
    const float* __restrict__ bih_f, const float* __restrict__ bhh_f,
    const float* __restrict__ bih_b, const float* __restrict__ bhh_b)
{
    __shared__ float As[64 * 68];
    __shared__ float Bs[64 * 68];
    __shared__ int   words[64];

    const int t     = blockIdx.x;
    const int ctile = blockIdx.y;
    const int d     = ctile >> 4;
    const int c0    = (ctile & 15) * 64;
    const int tid   = threadIdx.x;

    const float* __restrict__ wih = d ? wih_b : wih_f;
    const float* __restrict__ bih = d ? bih_b : bih_f;
    const float* __restrict__ bhh = d ? bhh_b : bhh_f;

    if (tid < 64) words[tid] = sent[tid * 512 + t];
    __syncthreads();

    const int ty = tid >> 4;
    const int tx = tid & 15;
    const int fr = tid >> 2;
    const int fq = tid & 3;

    unsigned long long acc[4][4];
    #pragma unroll
    for (int i = 0; i < 4; i++)
        #pragma unroll
        for (int j = 0; j < 4; j++) acc[i][j] = 0ull;

    const size_t wrow = (size_t)(c0 + fr) * 300;
    const size_t erow = (size_t)words[fr] * 300;

    for (int k0 = 0; k0 < 300; k0 += 60) {
        const float* __restrict__ wsrc = wih + wrow + k0;
        const float* __restrict__ esrc = embed + erow + k0;
        #pragma unroll
        for (int u = 0; u < 4; u++) {
            int q = fq + 4 * u;
            if (q < 15) {
                *(float4*)&As[fr * 68 + q * 4] = *(const float4*)&wsrc[q * 4];
                *(float4*)&Bs[fr * 68 + q * 4] = *(const float4*)&esrc[q * 4];
            }
        }
        __syncthreads();
        #pragma unroll 6
        for (int kk = 0; kk < 30; kk++) {
            const int k = 2 * kk;
            unsigned long long a2[4], b2[4];
            #pragma unroll
            for (int i = 0; i < 4; i++)
                a2[i] = *(const unsigned long long*)&As[(ty + 16 * i) * 68 + k];
            #pragma unroll
            for (int j = 0; j < 4; j++)
                b2[j] = *(const unsigned long long*)&Bs[(tx + 16 * j) * 68 + k];
            #pragma unroll
            for (int i = 0; i < 4; i++)
                #pragma unroll
                for (int j = 0; j < 4; j++)
                    acc[i][j] = ffma2(a2[i], b2[j], acc[i][j]);
        }
        __syncthreads();
    }

    const size_t obase = ((size_t)d * 512 + t) * 65536;
    #pragma unroll
    for (int i = 0; i < 4; i++) {
        int c = c0 + ty + 16 * i;
        float bias = bih[c] + bhh[c];
        #pragma unroll
        for (int j = 0; j < 4; j++)
            g_xp[obase + (size_t)c * 64 + tx + 16 * j] = hsum2(acc[i][j]) + bias;
    }
}

// ===========================================================================
// K2: persistent bidirectional LSTM recurrence (warp-decoupled).
//   128 CTAs (64/dir), 256 thr; CTA m owns cols [4m,4m+4).
//   Thread map: hcl = tid&3, b = tid>>2  -> h LDS = 1 crossbar phase,
//   w LDS dedupes 4-way in-warp. Each warp polls the step counters itself
//   (relaxed loop + 1 acquire) and cp.asyncs exactly its own b-columns
//   (disjoint smem ranges -> __syncwarp only). One CTA __syncthreads per
//   step before the release arrival.
// ===========================================================================
__global__ void __launch_bounds__(256, 1) k_rec(
    const float* __restrict__ whh_f, const float* __restrict__ whh_b)
{
    extern __shared__ float dsm[];
    float* wint   = dsm;            // 4096 floats (16KB): f4[(hcl*4+g)*64+jq]
    float* hstage = dsm + 4096;     // 16384 floats (64KB): f4[jq*64+b]

    const int bx   = blockIdx.x;
    const int d    = bx >> 6;
    const int m    = bx & 63;
    const int hc0  = m * 4;
    const int tid  = threadIdx.x;
    const int hcl  = tid & 3;       // 0..3 : local column (in-warp replication)
    const int b    = tid >> 2;      // 0..63
    const int lane = tid & 31;
    const float* __restrict__ whh = d ? whh_b : whh_f;

    for (int q = tid; q < 1024; q += 256) {
        int row = q >> 6, jq = q & 63;
        int g = row & 3, hl = row >> 2;
        *(float4*)&wint[q * 4] =
            *(const float4*)&whh[(size_t)(g * 256 + hc0 + hl) * 256 + 4 * jq];
    }
    __syncthreads();

    const ulonglong2* __restrict__ w2 = (const ulonglong2*)wint;
    const float4* __restrict__ hst4 = (const float4*)hstage;
    const unsigned hstage_s = (unsigned)__cvta_generic_to_shared(hstage);
    const int wr0 = (hcl * 4 + 0) * 64;
    const int wr1 = (hcl * 4 + 1) * 64;
    const int wr2 = (hcl * 4 + 2) * 64;
    const int wr3 = (hcl * 4 + 3) * 64;

    int* __restrict__ cbase = &g_cnt[d * 512];

    float cstate = 0.f;

    const int tt_first = d ? 511 : 0;
    size_t xb = ((size_t)d * 512 + tt_first) * 65536;
    float xi = g_xp[xb + (size_t)(hc0 + hcl) * 64 + b];
    float xf = g_xp[xb + (size_t)(256 + hc0 + hcl) * 64 + b];
    float xg = g_xp[xb + (size_t)(512 + hc0 + hcl) * 64 + b];
    float xo = g_xp[xb + (size_t)(768 + hc0 + hcl) * 64 + b];

    for (int t = 0; t < 512; t++) {
        const int tt = d ? (511 - t) : t;

        float ai, af, ag, ao;

        if (t > 0) {
            // per-warp poll: all 64 CTAs of this dir must have finished t-1
            if (lane == 0) {
                const int target = 64 * t;
                int s;
                do {
                    s = 0;
                    #pragma unroll
                    for (int i = 0; i < 8; i++) {
                        int v;
                        asm volatile("ld.relaxed.gpu.global.s32 %0, [%1];"
                                     : "=r"(v) : "l"(cbase + i * 32));
                        s += v;
                    }
                } while (s < target);
                int dummy;
                asm volatile("ld.acquire.gpu.global.s32 %0, [%1];"
                             : "=r"(dummy) : "l"(cbase) : "memory");
            }
            __syncwarp();

            const int hp = d ? (tt + 1) : (tt - 1);
            const float4* __restrict__ srcF4 =
                (const float4*)&g_hP[((size_t)hp * 2 + d) * 16384];

            // per-warp self-staging: lane copies quads (jq = 16g+hcl+4k, b)
            #pragma unroll
            for (int q = 0; q < 4; q++) {
                #pragma unroll
                for (int k = 0; k < 4; k++) {
                    int jq = 16 * q + hcl + 4 * k;
                    int f4i = jq * 64 + b;
                    unsigned sa = hstage_s + (unsigned)f4i * 16u;
                    asm volatile("cp.async.cg.shared.global [%0], [%1], 16;"
                                 :: "r"(sa), "l"(srcF4 + f4i) : "memory");
                }
                asm volatile("cp.async.commit_group;" ::: "memory");
            }

            unsigned long long a0 = 0, a1 = 0, a2 = 0, a3 = 0;

            #define GEMM_CHUNK(Q, W)                                            \
                asm volatile("cp.async.wait_group %0;" :: "n"(W) : "memory");   \
                __syncwarp();                                                   \
                _Pragma("unroll")                                               \
                for (int jq = (Q) * 16; jq < (Q) * 16 + 16; jq++) {             \
                    ulonglong2 h2 = *(const ulonglong2*)&hst4[jq * 64 + b];     \
                    ulonglong2 q0 = w2[wr0 + jq];                               \
                    ulonglong2 q1 = w2[wr1 + jq];                               \
                    ulonglong2 q2 = w2[wr2 + jq];                               \
                    ulonglong2 q3 = w2[wr3 + jq];                               \
                    a0 = ffma2(q0.x, h2.x, a0); a0 = ffma2(q0.y, h2.y, a0);     \
                    a1 = ffma2(q1.x, h2.x, a1); a1 = ffma2(q1.y, h2.y, a1);     \
                    a2 = ffma2(q2.x, h2.x, a2); a2 = ffma2(q2.y, h2.y, a2);     \
                    a3 = ffma2(q3.x, h2.x, a3); a3 = ffma2(q3.y, h2.y, a3);     \
                }
            GEMM_CHUNK(0, 3)
            GEMM_CHUNK(1, 2)
            GEMM_CHUNK(2, 1)
            GEMM_CHUNK(3, 0)
            #undef GEMM_CHUNK

            ai = hsum2(a0) + xi; af = hsum2(a1) + xf;
            ag = hsum2(a2) + xg; ao = hsum2(a3) + xo;
        } else {
            ai = xi; af = xf; ag = xg; ao = xo;
        }

        const float si = sig_ap(ai);
        const float sf = sig_ap(af);
        const float so = sig_ap(ao);
        cstate = sf * cstate + si * tanh_ap(ag);
        const float hval = so * tanh_ap(cstate);

        g_hP[((size_t)tt * 2 + d) * 16384 + (size_t)(m * 64 + b) * 4 + hcl] = hval;

        if (t < 511) {
            const int tn = d ? (510 - t) : (t + 1);
            const size_t xnb = ((size_t)d * 512 + tn) * 65536;
            xi = g_xp[xnb + (size_t)(hc0 + hcl) * 64 + b];
            xf = g_xp[xnb + (size_t)(256 + hc0 + hcl) * 64 + b];
            xg = g_xp[xnb + (size_t)(512 + hc0 + hcl) * 64 + b];
            xo = g_xp[xnb + (size_t)(768 + hc0 + hcl) * 64 + b];
        }

        // CTA arrival: one release-red per CTA per step
        __syncthreads();
        if (tid == 0) {
            asm volatile("red.release.gpu.global.add.s32 [%0], 1;"
                         :: "l"(cbase + (m & 7) * 32) : "memory");
        }
    }
}

// ===========================================================================
// K3: emissions from g_hP + barrier-counter reset for next graph replay.
// ===========================================================================
__global__ void __launch_bounds__(256) k_emis(
    const float* __restrict__ w_out, const float* __restrict__ b_out)
{
    if (blockIdx.x == 0 && threadIdx.x < 16)
        g_cnt[(threadIdx.x >> 3) * 512 + (threadIdx.x & 7) * 32] = 0;

    __shared__ float w_s[9 * 512];
    __shared__ float red[4][64][10];

    const int t = blockIdx.x, tid = threadIdx.x;
    for (int i = tid; i < 9 * 512; i += 256) w_s[i] = w_out[i];
    __syncthreads();

    const int b = tid & 63, seg = tid >> 6;
    const int d = seg >> 1, jq0 = (seg & 1) * 32;
    float acc[9] = {};
    const float4* __restrict__ hp4 =
        (const float4*)&g_hP[((size_t)t * 2 + d) * 16384];
    for (int jq = jq0; jq < jq0 + 32; jq++) {
        float4 h4 = hp4[jq * 64 + b];
        const int cb = d * 256 + 4 * jq;
        #pragma unroll
        for (int tau = 0; tau < 9; tau++) {
            acc[tau] += h4.x * w_s[tau * 512 + cb + 0]
                      + h4.y * w_s[tau * 512 + cb + 1]
                      + h4.z * w_s[tau * 512 + cb + 2]
                      + h4.w * w_s[tau * 512 + cb + 3];
        }
    }
    #pragma unroll
    for (int tau = 0; tau < 9; tau++) red[seg][b][tau] = acc[tau];
    __syncthreads();
    if (seg == 0) {
        #pragma unroll
        for (int tau = 0; tau < 9; tau++) {
            float v = red[0][b][tau] + red[1][b][tau] + red[2][b][tau] +
                      red[3][b][tau] + b_out[tau];
            g_emis[(size_t)t * 576 + b * 9 + tau] = v;
        }
    }
}

// ===========================================================================
// K4: CRF gold score + forward algorithm (logZ). grid 64 (b), 1 warp each.
// ===========================================================================
__global__ void k_crf(
    const int*   __restrict__ tags, const int* __restrict__ mask,
    const float* __restrict__ start_trans, const float* __restrict__ end_trans,
    const float* __restrict__ trans)
{
    const int b = blockIdx.x, lane = threadIdx.x;

    float sc = 0.f; int cnt = 0;
    for (int t = lane; t < 512; t += 32) {
        int mk = mask[b * 512 + t];
        cnt += mk;
        if (t >= 1 && mk) {
            int tp = tags[b * 512 + t - 1];
            int tc = tags[b * 512 + t];
            sc += trans[tp * 9 + tc] + g_emis[(size_t)t * 576 + b * 9 + tc];
        }
    }
    #pragma unroll
    for (int o = 16; o > 0; o >>= 1) {
        sc  += __shfl_down_sync(0xffffffffu, sc, o);
        cnt += __shfl_down_sync(0xffffffffu, cnt, o);
    }
    int len = __shfl_sync(0xffffffffu, cnt, 0);
    float score = 0.f;
    if (lane == 0) {
        int t0 = tags[b * 512];
        score = sc + start_trans[t0] + g_emis[b * 9 + t0];
        int tl = tags[b * 512 + len - 1];
        score += end_trans[tl];
    }

    float logZ = 0.f;
    if (lane < 9) {
        const int j = lane;
        float E[9];
        #pragma unroll
        for (int i = 0; i < 9; i++) E[i] = __expf(trans[i * 9 + j]);

        float a = start_trans[j] + g_emis[b * 9 + j];
        float a0 = __shfl_sync(0x1ffu, a, 0);
        float base = a0;
        a -= a0;

        float em_n = g_emis[(size_t)576 + b * 9 + j];
        int   mk_n = mask[b * 512 + 1];

        for (int t = 1; t < 512; t++) {
            if (!mk_n) break;
            float em = em_n;
            if (t < 511) {
                em_n = g_emis[(size_t)(t + 1) * 576 + b * 9 + j];
                mk_n = mask[b * 512 + t + 1];
            } else {
                mk_n = 0;
            }
            float ea = __expf(a);
            float s0 = 0.f, s1 = 0.f, s2 = 0.f;
            #pragma unroll
            for (int i = 0; i < 9; i += 3) {
                float e0 = __shfl_sync(0x1ffu, ea, i);
                float e1 = __shfl_sync(0x1ffu, ea, i + 1);
                float e2 = __shfl_sync(0x1ffu, ea, i + 2);
                s0 += e0 * E[i];
                s1 += e1 * E[i + 1];
                s2 += e2 * E[i + 2];
            }
            float u = __logf(s0 + s1 + s2) + em;
            float u0 = __shfl_sync(0x1ffu, u, 0);
            base += u0;
            a = u - u0;
        }
        float z = a + end_trans[j];
        float ez = __expf(z);
        float s = 0.f;
        #pragma unroll
        for (int i = 0; i < 9; i++) s += __shfl_sync(0x1ffu, ez, i);
        logZ = base + __logf(s);
    }
    if (lane == 0) g_llh[b] = score - logZ;
}

// ===========================================================================
// K5: final deterministic reduction  out = -mean(llh)
// ===========================================================================
__global__ void k_final(float* __restrict__ out)
{
    __shared__ float s[64];
    const int tid = threadIdx.x;
    s[tid] = g_llh[tid];
    __syncthreads();
    if (tid == 0) {
        float acc = 0.f;
        for (int i = 0; i < 64; i++) acc += s[i];
        out[0] = -acc / 64.f;
    }
}

// ===========================================================================
extern "C" void kernel_launch(void* const* d_in, const int* in_sizes, int n_in,
                              void* d_out, int out_size)
{
    const bool dictOrder = (in_sizes[2] == 15000000);
    const int ie = dictOrder ? 2 : 3;
    const int im = dictOrder ? 16 : 2;

    const int*   sent    = (const int*)  d_in[0];
    const int*   tags    = (const int*)  d_in[1];
    const float* embed   = (const float*)d_in[ie + 0];
    const float* wih_f   = (const float*)d_in[ie + 1];
    const float* whh_f   = (const float*)d_in[ie + 2];
    const float* bih_f   = (const float*)d_in[ie + 3];
    const float* bhh_f   = (const float*)d_in[ie + 4];
    const float* wih_b   = (const float*)d_in[ie + 5];
    const float* whh_b   = (const float*)d_in[ie + 6];
    const float* bih_b   = (const float*)d_in[ie + 7];
    const float* bhh_b   = (const float*)d_in[ie + 8];
    const float* w_out   = (const float*)d_in[ie + 9];
    const float* b_out   = (const float*)d_in[ie + 10];
    const float* s_tr    = (const float*)d_in[ie + 11];
    const float* e_tr    = (const float*)d_in[ie + 12];
    const float* trans   = (const float*)d_in[ie + 13];
    const int*   mask    = (const int*)  d_in[im];
    float*       out     = (float*)d_out;

    cudaFuncSetAttribute(k_rec, cudaFuncAttributeMaxDynamicSharedMemorySize, 81920);

    // shift the ncu -s/-c profiled slot onto k_rec
    k_pre1<<<1, 32>>>();
    k_pre2<<<1, 32>>>();

    dim3 g1(512, 32);
    k_inproj<<<g1, 256>>>(sent, embed, wih_f, wih_b, bih_f, bhh_f, bih_b, bhh_b);
    k_rec<<<128, 256, 81920>>>(whh_f, whh_b);
    k_emis<<<512, 256>>>(w_out, b_out);
    k_crf<<<64, 32>>>(tags, mask, s_tr, e_tr, trans);
    k_final<<<1, 64>>>(out);
}

// round 8
// speedup vs baseline: 2.4021x; 2.4021x over previous
#include <cuda_runtime.h>
#include <math.h>
#include <stdint.h>

// ---------------- device scratch ----------------
__device__ float g_xp[(size_t)2 * 512 * 1024 * 64];   // [dir][t][gate_row 0..1023][b]
__device__ float g_hP[(size_t)512 * 2 * 64 * 64 * 4]; // [t][d][jq][b][4]  (64MB)
__device__ float g_emis[(size_t)512 * 64 * 9];        // [t][b][tau]
__device__ float g_llh[64];
__device__ int   g_cnt[1024];                         // sub-counters: [d*512 + sub*32]

// ---------------- packed f32x2 helpers (Blackwell FFMA2) ----------------
__device__ __forceinline__ unsigned long long ffma2(unsigned long long a,
                                                    unsigned long long b,
                                                    unsigned long long c) {
    unsigned long long d;
    asm("fma.rn.f32x2 %0, %1, %2, %3;" : "=l"(d) : "l"(a), "l"(b), "l"(c));
    return d;
}
__device__ __forceinline__ float hsum2(unsigned long long v) {
    float lo, hi;
    asm("mov.b64 {%0, %1}, %2;" : "=f"(lo), "=f"(hi) : "l"(v));
    return lo + hi;
}
__device__ __forceinline__ float tanh_ap(float x) {
    float y;
    asm("tanh.approx.f32 %0, %1;" : "=f"(y) : "f"(x));
    return y;
}
__device__ __forceinline__ float sig_ap(float x) {
    return 0.5f * tanh_ap(0.5f * x) + 0.5f;
}

// ---------------- profiling-slot shifters (no-op) ----------------
__global__ void k_pre1() {}
__global__ void k_pre2() {}

// ===========================================================================
// K1: fused embedding gather + input projection GEMM (+ bih+bhh bias)
// ===========================================================================
__global__ void __launch_bounds__(256) k_inproj(
    const int*   __restrict__ sent,
    const float* __restrict__ embed,
    const float* __restrict__ wih_f, const float* __restrict__ wih_b,
    const float* __restrict__ bih_f, const float* __restrict__ bhh_f,
    const float* __restrict__ bih_b, const float* __restrict__ bhh_b)
{
    __shared__ float As[64 * 68];
    __shared__ float Bs[64 * 68];
    __shared__ int   words[64];

    const int t     = blockIdx.x;
    const int ctile = blockIdx.y;
    const int d     = ctile >> 4;
    const int c0    = (ctile & 15) * 64;
    const int tid   = threadIdx.x;

    const float* __restrict__ wih = d ? wih_b : wih_f;
    const float* __restrict__ bih = d ? bih_b : bih_f;
    const float* __restrict__ bhh = d ? bhh_b : bhh_f;

    if (tid < 64) words[tid] = sent[tid * 512 + t];
    __syncthreads();

    const int ty = tid >> 4;
    const int tx = tid & 15;
    const int fr = tid >> 2;
    const int fq = tid & 3;

    unsigned long long acc[4][4];
    #pragma unroll
    for (int i = 0; i < 4; i++)
        #pragma unroll
        for (int j = 0; j < 4; j++) acc[i][j] = 0ull;

    const size_t wrow = (size_t)(c0 + fr) * 300;
    const size_t erow = (size_t)words[fr] * 300;

    for (int k0 = 0; k0 < 300; k0 += 60) {
        const float* __restrict__ wsrc = wih + wrow + k0;
        const float* __restrict__ esrc = embed + erow + k0;
        #pragma unroll
        for (int u = 0; u < 4; u++) {
            int q = fq + 4 * u;
            if (q < 15) {
                *(float4*)&As[fr * 68 + q * 4] = *(const float4*)&wsrc[q * 4];
                *(float4*)&Bs[fr * 68 + q * 4] = *(const float4*)&esrc[q * 4];
            }
        }
        __syncthreads();
        #pragma unroll 6
        for (int kk = 0; kk < 30; kk++) {
            const int k = 2 * kk;
            unsigned long long a2[4], b2[4];
            #pragma unroll
            for (int i = 0; i < 4; i++)
                a2[i] = *(const unsigned long long*)&As[(ty + 16 * i) * 68 + k];
            #pragma unroll
            for (int j = 0; j < 4; j++)
                b2[j] = *(const unsigned long long*)&Bs[(tx + 16 * j) * 68 + k];
            #pragma unroll
            for (int i = 0; i < 4; i++)
                #pragma unroll
                for (int j = 0; j < 4; j++)
                    acc[i][j] = ffma2(a2[i], b2[j], acc[i][j]);
        }
        __syncthreads();
    }

    const size_t obase = ((size_t)d * 512 + t) * 65536;
    #pragma unroll
    for (int i = 0; i < 4; i++) {
        int c = c0 + ty + 16 * i;
        float bias = bih[c] + bhh[c];
        #pragma unroll
        for (int j = 0; j < 4; j++)
            g_xp[obase + (size_t)c * 64 + tx + 16 * j] = hsum2(acc[i][j]) + bias;
    }
}

// ===========================================================================
// K2: persistent bidirectional LSTM recurrence, b-register-blocked.
//   128 CTAs (64/dir), 128 thr; CTA m owns cols [4m,4m+4).
//   Thread = (hcl = tid&3, bq = tid>>2) computes 2 batch cols (2bq, 2bq+1):
//   8 f32x2 accumulators (4 gates x 2 b). Warp lanes span 4 hcl -> h-LDS
//   dedupes 4-way (1 phase, via b-permuted hstage); w-LDS: wint laid out
//   hcl-fastest so the 4 hcl lanes hit one contiguous 64B (1 phase).
//   cp.async staging in 4 chunks overlapped with GEMM; per-CTA tid0 poll
//   of monotone 8-sub-counter barrier (R5 scheme, counters reset by k_emis).
// ===========================================================================
__global__ void __launch_bounds__(128, 1) k_rec(
    const float* __restrict__ whh_f, const float* __restrict__ whh_b)
{
    extern __shared__ float dsm[];
    float* wint   = dsm;            // 1024 f4 (16KB): f4[(g*64+jq)*4 + hcl]
    float* hstage = dsm + 4096;     // 4096 f4 (64KB): f4[jq*64 + perm(b)]

    const int bx  = blockIdx.x;
    const int d   = bx >> 6;
    const int m   = bx & 63;
    const int hc0 = m * 4;
    const int tid = threadIdx.x;
    const int hcl = tid & 3;        // 0..3 local column
    const int bq  = tid >> 2;       // 0..31 -> b in {2bq, 2bq+1}
    const float* __restrict__ whh = d ? whh_b : whh_f;

    // wint fill: f4 idx = (g*64+jq)*4 + hcl  <-  whh[(g*256+hc0+hcl)*256 + 4jq]
    for (int idx = tid; idx < 1024; idx += 128) {
        int hl = idx & 3, rest = idx >> 2;
        int jq = rest & 63, g = rest >> 6;
        *(float4*)&wint[idx * 4] =
            *(const float4*)&whh[(size_t)(g * 256 + hc0 + hl) * 256 + 4 * jq];
    }
    __syncthreads();

    const ulonglong2* __restrict__ w2 = (const ulonglong2*)wint;
    const ulonglong2* __restrict__ h2p = (const ulonglong2*)hstage;
    const unsigned hstage_s = (unsigned)__cvta_generic_to_shared(hstage);

    // permuted b indices for this thread's two columns (bank-conflict-free)
    const int pb0 = bq;        // perm(2bq)   = bq
    const int pb1 = bq + 32;   // perm(2bq+1) = bq + 32

    int* __restrict__ cbase = &g_cnt[d * 512];

    float cs0 = 0.f, cs1 = 0.f;

    const int tt_first = d ? 511 : 0;
    {
        // nothing extra
    }
    size_t xb = ((size_t)d * 512 + tt_first) * 65536;
    float2 xI = *(const float2*)&g_xp[xb + (size_t)(0 * 256 + hc0 + hcl) * 64 + 2 * bq];
    float2 xF = *(const float2*)&g_xp[xb + (size_t)(1 * 256 + hc0 + hcl) * 64 + 2 * bq];
    float2 xG = *(const float2*)&g_xp[xb + (size_t)(2 * 256 + hc0 + hcl) * 64 + 2 * bq];
    float2 xO = *(const float2*)&g_xp[xb + (size_t)(3 * 256 + hc0 + hcl) * 64 + 2 * bq];

    for (int t = 0; t < 512; t++) {
        const int tt = d ? (511 - t) : t;

        float ai0, af0, ag0, ao0, ai1, af1, ag1, ao1;

        if (t > 0) {
            // wait for all 64 CTAs of this direction to finish step t-1
            if (tid == 0) {
                const int target = 64 * t;
                int s;
                do {
                    s = 0;
                    #pragma unroll
                    for (int i = 0; i < 8; i++) {
                        int v;
                        asm volatile("ld.relaxed.gpu.global.s32 %0, [%1];"
                                     : "=r"(v) : "l"(cbase + i * 32));
                        s += v;
                    }
                } while (s < target);
                int dummy;
                asm volatile("ld.acquire.gpu.global.s32 %0, [%1];"
                             : "=r"(dummy) : "l"(cbase) : "memory");
            }
            __syncthreads();

            const int hp = d ? (tt + 1) : (tt - 1);
            const float4* __restrict__ srcF4 =
                (const float4*)&g_hP[((size_t)hp * 2 + d) * 16384];

            // staging with b-permute: src f4 (jq*64+b) -> dst f4 (jq*64+perm(b))
            #pragma unroll
            for (int q = 0; q < 4; q++) {
                #pragma unroll
                for (int r = 0; r < 8; r++) {
                    int f4i = q * 1024 + r * 128 + tid;
                    int b_  = f4i & 63;
                    int dst = (f4i & ~63) | ((b_ >> 1) | ((b_ & 1) << 5));
                    unsigned sa = hstage_s + (unsigned)dst * 16u;
                    asm volatile("cp.async.cg.shared.global [%0], [%1], 16;"
                                 :: "r"(sa), "l"(srcF4 + f4i) : "memory");
                }
                asm volatile("cp.async.commit_group;" ::: "memory");
            }

            unsigned long long a00 = 0, a01 = 0, a10 = 0, a11 = 0;
            unsigned long long a20 = 0, a21 = 0, a30 = 0, a31 = 0;

            #define GEMM_CHUNK(Q, W)                                            \
                asm volatile("cp.async.wait_group %0;" :: "n"(W) : "memory");   \
                __syncthreads();                                                \
                _Pragma("unroll")                                               \
                for (int jq = (Q) * 16; jq < (Q) * 16 + 16; jq++) {             \
                    ulonglong2 h0 = h2p[jq * 64 + pb0];                         \
                    ulonglong2 h1 = h2p[jq * 64 + pb1];                         \
                    ulonglong2 q0 = w2[(0 * 64 + jq) * 4 + hcl];                \
                    ulonglong2 q1 = w2[(1 * 64 + jq) * 4 + hcl];                \
                    ulonglong2 q2 = w2[(2 * 64 + jq) * 4 + hcl];                \
                    ulonglong2 q3 = w2[(3 * 64 + jq) * 4 + hcl];                \
                    a00 = ffma2(q0.x, h0.x, a00); a00 = ffma2(q0.y, h0.y, a00); \
                    a01 = ffma2(q0.x, h1.x, a01); a01 = ffma2(q0.y, h1.y, a01); \
                    a10 = ffma2(q1.x, h0.x, a10); a10 = ffma2(q1.y, h0.y, a10); \
                    a11 = ffma2(q1.x, h1.x, a11); a11 = ffma2(q1.y, h1.y, a11); \
                    a20 = ffma2(q2.x, h0.x, a20); a20 = ffma2(q2.y, h0.y, a20); \
                    a21 = ffma2(q2.x, h1.x, a21); a21 = ffma2(q2.y, h1.y, a21); \
                    a30 = ffma2(q3.x, h0.x, a30); a30 = ffma2(q3.y, h0.y, a30); \
                    a31 = ffma2(q3.x, h1.x, a31); a31 = ffma2(q3.y, h1.y, a31); \
                }
            GEMM_CHUNK(0, 3)
            GEMM_CHUNK(1, 2)
            GEMM_CHUNK(2, 1)
            GEMM_CHUNK(3, 0)
            #undef GEMM_CHUNK

            ai0 = hsum2(a00) + xI.x; ai1 = hsum2(a01) + xI.y;
            af0 = hsum2(a10) + xF.x; af1 = hsum2(a11) + xF.y;
            ag0 = hsum2(a20) + xG.x; ag1 = hsum2(a21) + xG.y;
            ao0 = hsum2(a30) + xO.x; ao1 = hsum2(a31) + xO.y;
        } else {
            ai0 = xI.x; ai1 = xI.y; af0 = xF.x; af1 = xF.y;
            ag0 = xG.x; ag1 = xG.y; ao0 = xO.x; ao1 = xO.y;
        }

        cs0 = sig_ap(af0) * cs0 + sig_ap(ai0) * tanh_ap(ag0);
        cs1 = sig_ap(af1) * cs1 + sig_ap(ai1) * tanh_ap(ag1);
        const float hv0 = sig_ap(ao0) * tanh_ap(cs0);
        const float hv1 = sig_ap(ao1) * tanh_ap(cs1);

        const size_t sbase = ((size_t)tt * 2 + d) * 16384;
        g_hP[sbase + (size_t)(m * 64 + 2 * bq + 0) * 4 + hcl] = hv0;
        g_hP[sbase + (size_t)(m * 64 + 2 * bq + 1) * 4 + hcl] = hv1;

        // prefetch next step's x gates
        if (t < 511) {
            const int tn = d ? (510 - t) : (t + 1);
            const size_t xnb = ((size_t)d * 512 + tn) * 65536;
            xI = *(const float2*)&g_xp[xnb + (size_t)(0 * 256 + hc0 + hcl) * 64 + 2 * bq];
            xF = *(const float2*)&g_xp[xnb + (size_t)(1 * 256 + hc0 + hcl) * 64 + 2 * bq];
            xG = *(const float2*)&g_xp[xnb + (size_t)(2 * 256 + hc0 + hcl) * 64 + 2 * bq];
            xO = *(const float2*)&g_xp[xnb + (size_t)(3 * 256 + hc0 + hcl) * 64 + 2 * bq];
        }

        // CTA arrival: one release-red per CTA per step
        __syncthreads();
        if (tid == 0) {
            asm volatile("red.release.gpu.global.add.s32 [%0], 1;"
                         :: "l"(cbase + (m & 7) * 32) : "memory");
        }
    }
}

// ===========================================================================
// K3: emissions from g_hP + barrier-counter reset for next graph replay.
// ===========================================================================
__global__ void __launch_bounds__(256) k_emis(
    const float* __restrict__ w_out, const float* __restrict__ b_out)
{
    if (blockIdx.x == 0 && threadIdx.x < 16)
        g_cnt[(threadIdx.x >> 3) * 512 + (threadIdx.x & 7) * 32] = 0;

    __shared__ float w_s[9 * 512];
    __shared__ float red[4][64][10];

    const int t = blockIdx.x, tid = threadIdx.x;
    for (int i = tid; i < 9 * 512; i += 256) w_s[i] = w_out[i];
    __syncthreads();

    const int b = tid & 63, seg = tid >> 6;
    const int d = seg >> 1, jq0 = (seg & 1) * 32;
    float acc[9] = {};
    const float4* __restrict__ hp4 =
        (const float4*)&g_hP[((size_t)t * 2 + d) * 16384];
    for (int jq = jq0; jq < jq0 + 32; jq++) {
        float4 h4 = hp4[jq * 64 + b];
        const int cb = d * 256 + 4 * jq;
        #pragma unroll
        for (int tau = 0; tau < 9; tau++) {
            acc[tau] += h4.x * w_s[tau * 512 + cb + 0]
                      + h4.y * w_s[tau * 512 + cb + 1]
                      + h4.z * w_s[tau * 512 + cb + 2]
                      + h4.w * w_s[tau * 512 + cb + 3];
        }
    }
    #pragma unroll
    for (int tau = 0; tau < 9; tau++) red[seg][b][tau] = acc[tau];
    __syncthreads();
    if (seg == 0) {
        #pragma unroll
        for (int tau = 0; tau < 9; tau++) {
            float v = red[0][b][tau] + red[1][b][tau] + red[2][b][tau] +
                      red[3][b][tau] + b_out[tau];
            g_emis[(size_t)t * 576 + b * 9 + tau] = v;
        }
    }
}

// ===========================================================================
// K4: CRF gold score + forward algorithm (logZ). grid 64 (b), 1 warp each.
// ===========================================================================
__global__ void k_crf(
    const int*   __restrict__ tags, const int* __restrict__ mask,
    const float* __restrict__ start_trans, const float* __restrict__ end_trans,
    const float* __restrict__ trans)
{
    const int b = blockIdx.x, lane = threadIdx.x;

    float sc = 0.f; int cnt = 0;
    for (int t = lane; t < 512; t += 32) {
        int mk = mask[b * 512 + t];
        cnt += mk;
        if (t >= 1 && mk) {
            int tp = tags[b * 512 + t - 1];
            int tc = tags[b * 512 + t];
            sc += trans[tp * 9 + tc] + g_emis[(size_t)t * 576 + b * 9 + tc];
        }
    }
    #pragma unroll
    for (int o = 16; o > 0; o >>= 1) {
        sc  += __shfl_down_sync(0xffffffffu, sc, o);
        cnt += __shfl_down_sync(0xffffffffu, cnt, o);
    }
    int len = __shfl_sync(0xffffffffu, cnt, 0);
    float score = 0.f;
    if (lane == 0) {
        int t0 = tags[b * 512];
        score = sc + start_trans[t0] + g_emis[b * 9 + t0];
        int tl = tags[b * 512 + len - 1];
        score += end_trans[tl];
    }

    float logZ = 0.f;
    if (lane < 9) {
        const int j = lane;
        float E[9];
        #pragma unroll
        for (int i = 0; i < 9; i++) E[i] = __expf(trans[i * 9 + j]);

        float a = start_trans[j] + g_emis[b * 9 + j];
        float a0 = __shfl_sync(0x1ffu, a, 0);
        float base = a0;
        a -= a0;

        float em_n = g_emis[(size_t)576 + b * 9 + j];
        int   mk_n = mask[b * 512 + 1];

        for (int t = 1; t < 512; t++) {
            if (!mk_n) break;
            float em = em_n;
            if (t < 511) {
                em_n = g_emis[(size_t)(t + 1) * 576 + b * 9 + j];
                mk_n = mask[b * 512 + t + 1];
            } else {
                mk_n = 0;
            }
            float ea = __expf(a);
            float s0 = 0.f, s1 = 0.f, s2 = 0.f;
            #pragma unroll
            for (int i = 0; i < 9; i += 3) {
                float e0 = __shfl_sync(0x1ffu, ea, i);
                float e1 = __shfl_sync(0x1ffu, ea, i + 1);
                float e2 = __shfl_sync(0x1ffu, ea, i + 2);
                s0 += e0 * E[i];
                s1 += e1 * E[i + 1];
                s2 += e2 * E[i + 2];
            }
            float u = __logf(s0 + s1 + s2) + em;
            float u0 = __shfl_sync(0x1ffu, u, 0);
            base += u0;
            a = u - u0;
        }
        float z = a + end_trans[j];
        float ez = __expf(z);
        float s = 0.f;
        #pragma unroll
        for (int i = 0; i < 9; i++) s += __shfl_sync(0x1ffu, ez, i);
        logZ = base + __logf(s);
    }
    if (lane == 0) g_llh[b] = score - logZ;
}

// ===========================================================================
// K5: final deterministic reduction  out = -mean(llh)
// ===========================================================================
__global__ void k_final(float* __restrict__ out)
{
    __shared__ float s[64];
    const int tid = threadIdx.x;
    s[tid] = g_llh[tid];
    __syncthreads();
    if (tid == 0) {
        float acc = 0.f;
        for (int i = 0; i < 64; i++) acc += s[i];
        out[0] = -acc / 64.f;
    }
}

// ===========================================================================
extern "C" void kernel_launch(void* const* d_in, const int* in_sizes, int n_in,
                              void* d_out, int out_size)
{
    const bool dictOrder = (in_sizes[2] == 15000000);
    const int ie = dictOrder ? 2 : 3;
    const int im = dictOrder ? 16 : 2;

    const int*   sent    = (const int*)  d_in[0];
    const int*   tags    = (const int*)  d_in[1];
    const float* embed   = (const float*)d_in[ie + 0];
    const float* wih_f   = (const float*)d_in[ie + 1];
    const float* whh_f   = (const float*)d_in[ie + 2];
    const float* bih_f   = (const float*)d_in[ie + 3];
    const float* bhh_f   = (const float*)d_in[ie + 4];
    const float* wih_b   = (const float*)d_in[ie + 5];
    const float* whh_b   = (const float*)d_in[ie + 6];
    const float* bih_b   = (const float*)d_in[ie + 7];
    const float* bhh_b   = (const float*)d_in[ie + 8];
    const float* w_out   = (const float*)d_in[ie + 9];
    const float* b_out   = (const float*)d_in[ie + 10];
    const float* s_tr    = (const float*)d_in[ie + 11];
    const float* e_tr    = (const float*)d_in[ie + 12];
    const float* trans   = (const float*)d_in[ie + 13];
    const int*   mask    = (const int*)  d_in[im];
    float*       out     = (float*)d_out;

    cudaFuncSetAttribute(k_rec, cudaFuncAttributeMaxDynamicSharedMemorySize, 81920);

    // shift the ncu -s/-c profiled slot onto k_rec
    k_pre1<<<1, 32>>>();
    k_pre2<<<1, 32>>>();

    dim3 g1(512, 32);
    k_inproj<<<g1, 256>>>(sent, embed, wih_f, wih_b, bih_f, bhh_f, bih_b, bhh_b);
    k_rec<<<128, 128, 81920>>>(whh_f, whh_b);
    k_emis<<<512, 256>>>(w_out, b_out);
    k_crf<<<64, 32>>>(tags, mask, s_tr, e_tr, trans);
    k_final<<<1, 64>>>(out);
}

// round 9
// speedup vs baseline: 2.6941x; 1.1215x over previous
#include <cuda_runtime.h>
#include <math.h>
#include <stdint.h>

// ---------------- device scratch ----------------
__device__ float g_xp[(size_t)2 * 512 * 1024 * 64];   // [dir][t][gate_row 0..1023][b]
__device__ float g_hP[(size_t)512 * 2 * 64 * 64 * 4]; // [t][d][jq][b][4]  (64MB)
__device__ float g_emis[(size_t)512 * 64 * 9];        // [t][b][tau]
__device__ float g_llh[64];
__device__ int   g_cnt[1024];                         // sub-counters: [d*512 + sub*32]

// ---------------- packed f32x2 helpers (Blackwell FFMA2) ----------------
__device__ __forceinline__ unsigned long long ffma2(unsigned long long a,
                                                    unsigned long long b,
                                                    unsigned long long c) {
    unsigned long long d;
    asm("fma.rn.f32x2 %0, %1, %2, %3;" : "=l"(d) : "l"(a), "l"(b), "l"(c));
    return d;
}
__device__ __forceinline__ float hsum2(unsigned long long v) {
    float lo, hi;
    asm("mov.b64 {%0, %1}, %2;" : "=f"(lo), "=f"(hi) : "l"(v));
    return lo + hi;
}
__device__ __forceinline__ float tanh_ap(float x) {
    float y;
    asm("tanh.approx.f32 %0, %1;" : "=f"(y) : "f"(x));
    return y;
}
__device__ __forceinline__ float sig_ap(float x) {
    return 0.5f * tanh_ap(0.5f * x) + 0.5f;
}

// ---------------- profiling-slot shifters (no-op) ----------------
__global__ void k_pre1() {}
__global__ void k_pre2() {}

// ===========================================================================
// K1: fused embedding gather + input projection GEMM (+ bih+bhh bias)
// ===========================================================================
__global__ void __launch_bounds__(256) k_inproj(
    const int*   __restrict__ sent,
    const float* __restrict__ embed,
    const float* __restrict__ wih_f, const float* __restrict__ wih_b,
    const float* __restrict__ bih_f, const float* __restrict__ bhh_f,
    const float* __restrict__ bih_b, const float* __restrict__ bhh_b)
{
    __shared__ float As[64 * 68];
    __shared__ float Bs[64 * 68];
    __shared__ int   words[64];

    const int t     = blockIdx.x;
    const int ctile = blockIdx.y;
    const int d     = ctile >> 4;
    const int c0    = (ctile & 15) * 64;
    const int tid   = threadIdx.x;

    const float* __restrict__ wih = d ? wih_b : wih_f;
    const float* __restrict__ bih = d ? bih_b : bih_f;
    const float* __restrict__ bhh = d ? bhh_b : bhh_f;

    if (tid < 64) words[tid] = sent[tid * 512 + t];
    __syncthreads();

    const int ty = tid >> 4;
    const int tx = tid & 15;
    const int fr = tid >> 2;
    const int fq = tid & 3;

    unsigned long long acc[4][4];
    #pragma unroll
    for (int i = 0; i < 4; i++)
        #pragma unroll
        for (int j = 0; j < 4; j++) acc[i][j] = 0ull;

    const size_t wrow = (size_t)(c0 + fr) * 300;
    const size_t erow = (size_t)words[fr] * 300;

    for (int k0 = 0; k0 < 300; k0 += 60) {
        const float* __restrict__ wsrc = wih + wrow + k0;
        const float* __restrict__ esrc = embed + erow + k0;
        #pragma unroll
        for (int u = 0; u < 4; u++) {
            int q = fq + 4 * u;
            if (q < 15) {
                *(float4*)&As[fr * 68 + q * 4] = *(const float4*)&wsrc[q * 4];
                *(float4*)&Bs[fr * 68 + q * 4] = *(const float4*)&esrc[q * 4];
            }
        }
        __syncthreads();
        #pragma unroll 6
        for (int kk = 0; kk < 30; kk++) {
            const int k = 2 * kk;
            unsigned long long a2[4], b2[4];
            #pragma unroll
            for (int i = 0; i < 4; i++)
                a2[i] = *(const unsigned long long*)&As[(ty + 16 * i) * 68 + k];
            #pragma unroll
            for (int j = 0; j < 4; j++)
                b2[j] = *(const unsigned long long*)&Bs[(tx + 16 * j) * 68 + k];
            #pragma unroll
            for (int i = 0; i < 4; i++)
                #pragma unroll
                for (int j = 0; j < 4; j++)
                    acc[i][j] = ffma2(a2[i], b2[j], acc[i][j]);
        }
        __syncthreads();
    }

    const size_t obase = ((size_t)d * 512 + t) * 65536;
    #pragma unroll
    for (int i = 0; i < 4; i++) {
        int c = c0 + ty + 16 * i;
        float bias = bih[c] + bhh[c];
        #pragma unroll
        for (int j = 0; j < 4; j++)
            g_xp[obase + (size_t)c * 64 + tx + 16 * j] = hsum2(acc[i][j]) + bias;
    }
}

// ===========================================================================
// K2: persistent bidirectional LSTM recurrence.
//   128 CTAs (64/dir), 256 thr (8 warps); CTA m owns cols [4m,4m+4).
//   Thread = (hcl = tid&3, b = tid>>2). h read directly from L2 via __ldg
//   with an 8-deep register lookahead (no smem staging, no chunk syncs);
//   fresh t-indexed addresses每step + per-launch L1 flush => coherent.
//   w in smem laid out f4[jq*16 + g*4 + hcl]: 4-lane 64B contiguous loads.
//   Barrier: R5 single-poller monotone 8-sub-counter scheme (reset by k_emis).
// ===========================================================================
__global__ void __launch_bounds__(256, 1) k_rec(
    const float* __restrict__ whh_f, const float* __restrict__ whh_b)
{
    __shared__ __align__(16) float wint[4096];   // 16KB: f4 idx = jq*16+g*4+hcl

    const int bx  = blockIdx.x;
    const int d   = bx >> 6;
    const int m   = bx & 63;
    const int hc0 = m * 4;
    const int tid = threadIdx.x;
    const int hcl = tid & 3;        // 0..3 local column
    const int b   = tid >> 2;       // 0..63
    const float* __restrict__ whh = d ? whh_b : whh_f;

    // wint fill: f4 idx = jq*16 + g*4 + hl  <-  whh[(g*256+hc0+hl)*256 + 4jq]
    for (int idx = tid; idx < 1024; idx += 256) {
        int hl = idx & 3;
        int g  = (idx >> 2) & 3;
        int jq = idx >> 4;
        *(float4*)&wint[idx * 4] =
            *(const float4*)&whh[(size_t)(g * 256 + hc0 + hl) * 256 + 4 * jq];
    }
    __syncthreads();

    const ulonglong2* __restrict__ w2 = (const ulonglong2*)wint;
    int* __restrict__ cbase = &g_cnt[d * 512];

    float cs = 0.f;

    const int tt_first = d ? 511 : 0;
    size_t xb = ((size_t)d * 512 + tt_first) * 65536;
    float xi = g_xp[xb + (size_t)(0 * 256 + hc0 + hcl) * 64 + b];
    float xf = g_xp[xb + (size_t)(1 * 256 + hc0 + hcl) * 64 + b];
    float xg = g_xp[xb + (size_t)(2 * 256 + hc0 + hcl) * 64 + b];
    float xo = g_xp[xb + (size_t)(3 * 256 + hc0 + hcl) * 64 + b];

    for (int t = 0; t < 512; t++) {
        const int tt = d ? (511 - t) : t;

        float ai, af, ag, ao;

        if (t > 0) {
            // wait for all 64 CTAs of this direction to finish step t-1
            if (tid == 0) {
                const int target = 64 * t;
                int s;
                do {
                    s = 0;
                    #pragma unroll
                    for (int i = 0; i < 8; i++) {
                        int v;
                        asm volatile("ld.relaxed.gpu.global.s32 %0, [%1];"
                                     : "=r"(v) : "l"(cbase + i * 32));
                        s += v;
                    }
                } while (s < target);
                int dummy;
                asm volatile("ld.acquire.gpu.global.s32 %0, [%1];"
                             : "=r"(dummy) : "l"(cbase) : "memory");
            }
            __syncthreads();

            const int hp = d ? (tt + 1) : (tt - 1);
            const uint4* __restrict__ hsrc =
                (const uint4*)&g_hP[((size_t)hp * 2 + d) * 16384];

            // 8-deep lookahead of h quads [jq][b][k0..3]
            uint4 hbuf[8];
            #pragma unroll
            for (int i = 0; i < 8; i++) hbuf[i] = __ldg(&hsrc[i * 64 + b]);

            unsigned long long a0 = 0, a1 = 0, a2 = 0, a3 = 0;

            #pragma unroll
            for (int c = 0; c < 8; c++) {
                #pragma unroll
                for (int i = 0; i < 8; i++) {
                    const int jq = c * 8 + i;
                    uint4 hv = hbuf[i];
                    if (c < 7) hbuf[i] = __ldg(&hsrc[(jq + 8) * 64 + b]);
                    unsigned long long hx, hy;
                    asm("mov.b64 %0, {%1,%2};" : "=l"(hx) : "r"(hv.x), "r"(hv.y));
                    asm("mov.b64 %0, {%1,%2};" : "=l"(hy) : "r"(hv.z), "r"(hv.w));
                    ulonglong2 q0 = w2[jq * 16 + 0 * 4 + hcl];
                    ulonglong2 q1 = w2[jq * 16 + 1 * 4 + hcl];
                    ulonglong2 q2 = w2[jq * 16 + 2 * 4 + hcl];
                    ulonglong2 q3 = w2[jq * 16 + 3 * 4 + hcl];
                    a0 = ffma2(q0.x, hx, a0); a0 = ffma2(q0.y, hy, a0);
                    a1 = ffma2(q1.x, hx, a1); a1 = ffma2(q1.y, hy, a1);
                    a2 = ffma2(q2.x, hx, a2); a2 = ffma2(q2.y, hy, a2);
                    a3 = ffma2(q3.x, hx, a3); a3 = ffma2(q3.y, hy, a3);
                }
            }

            ai = hsum2(a0) + xi; af = hsum2(a1) + xf;
            ag = hsum2(a2) + xg; ao = hsum2(a3) + xo;
        } else {
            ai = xi; af = xf; ag = xg; ao = xo;
        }

        cs = sig_ap(af) * cs + sig_ap(ai) * tanh_ap(ag);
        const float hval = sig_ap(ao) * tanh_ap(cs);

        // store: [tt][d][jq=m][b][k=hcl]  (warp -> 128B coalesced)
        g_hP[((size_t)tt * 2 + d) * 16384 + (size_t)(m * 64 + b) * 4 + hcl] = hval;

        // prefetch next step's x gates
        if (t < 511) {
            const int tn = d ? (510 - t) : (t + 1);
            const size_t xnb = ((size_t)d * 512 + tn) * 65536;
            xi = g_xp[xnb + (size_t)(0 * 256 + hc0 + hcl) * 64 + b];
            xf = g_xp[xnb + (size_t)(1 * 256 + hc0 + hcl) * 64 + b];
            xg = g_xp[xnb + (size_t)(2 * 256 + hc0 + hcl) * 64 + b];
            xo = g_xp[xnb + (size_t)(3 * 256 + hc0 + hcl) * 64 + b];
        }

        // CTA arrival: one release-red per CTA per step
        __syncthreads();
        if (tid == 0) {
            asm volatile("red.release.gpu.global.add.s32 [%0], 1;"
                         :: "l"(cbase + (m & 7) * 32) : "memory");
        }
    }
}

// ===========================================================================
// K3: emissions from g_hP + barrier-counter reset for next graph replay.
// ===========================================================================
__global__ void __launch_bounds__(256) k_emis(
    const float* __restrict__ w_out, const float* __restrict__ b_out)
{
    if (blockIdx.x == 0 && threadIdx.x < 16)
        g_cnt[(threadIdx.x >> 3) * 512 + (threadIdx.x & 7) * 32] = 0;

    __shared__ float w_s[9 * 512];
    __shared__ float red[4][64][10];

    const int t = blockIdx.x, tid = threadIdx.x;
    for (int i = tid; i < 9 * 512; i += 256) w_s[i] = w_out[i];
    __syncthreads();

    const int b = tid & 63, seg = tid >> 6;
    const int d = seg >> 1, jq0 = (seg & 1) * 32;
    float acc[9] = {};
    const float4* __restrict__ hp4 =
        (const float4*)&g_hP[((size_t)t * 2 + d) * 16384];
    for (int jq = jq0; jq < jq0 + 32; jq++) {
        float4 h4 = hp4[jq * 64 + b];
        const int cb = d * 256 + 4 * jq;
        #pragma unroll
        for (int tau = 0; tau < 9; tau++) {
            acc[tau] += h4.x * w_s[tau * 512 + cb + 0]
                      + h4.y * w_s[tau * 512 + cb + 1]
                      + h4.z * w_s[tau * 512 + cb + 2]
                      + h4.w * w_s[tau * 512 + cb + 3];
        }
    }
    #pragma unroll
    for (int tau = 0; tau < 9; tau++) red[seg][b][tau] = acc[tau];
    __syncthreads();
    if (seg == 0) {
        #pragma unroll
        for (int tau = 0; tau < 9; tau++) {
            float v = red[0][b][tau] + red[1][b][tau] + red[2][b][tau] +
                      red[3][b][tau] + b_out[tau];
            g_emis[(size_t)t * 576 + b * 9 + tau] = v;
        }
    }
}

// ===========================================================================
// K4: CRF gold score + forward algorithm (logZ). grid 64 (b), 1 warp each.
// ===========================================================================
__global__ void k_crf(
    const int*   __restrict__ tags, const int* __restrict__ mask,
    const float* __restrict__ start_trans, const float* __restrict__ end_trans,
    const float* __restrict__ trans)
{
    const int b = blockIdx.x, lane = threadIdx.x;

    float sc = 0.f; int cnt = 0;
    for (int t = lane; t < 512; t += 32) {
        int mk = mask[b * 512 + t];
        cnt += mk;
        if (t >= 1 && mk) {
            int tp = tags[b * 512 + t - 1];
            int tc = tags[b * 512 + t];
            sc += trans[tp * 9 + tc] + g_emis[(size_t)t * 576 + b * 9 + tc];
        }
    }
    #pragma unroll
    for (int o = 16; o > 0; o >>= 1) {
        sc  += __shfl_down_sync(0xffffffffu, sc, o);
        cnt += __shfl_down_sync(0xffffffffu, cnt, o);
    }
    int len = __shfl_sync(0xffffffffu, cnt, 0);
    float score = 0.f;
    if (lane == 0) {
        int t0 = tags[b * 512];
        score = sc + start_trans[t0] + g_emis[b * 9 + t0];
        int tl = tags[b * 512 + len - 1];
        score += end_trans[tl];
    }

    float logZ = 0.f;
    if (lane < 9) {
        const int j = lane;
        float E[9];
        #pragma unroll
        for (int i = 0; i < 9; i++) E[i] = __expf(trans[i * 9 + j]);

        float a = start_trans[j] + g_emis[b * 9 + j];
        float a0 = __shfl_sync(0x1ffu, a, 0);
        float base = a0;
        a -= a0;

        float em_n = g_emis[(size_t)576 + b * 9 + j];
        int   mk_n = mask[b * 512 + 1];

        for (int t = 1; t < 512; t++) {
            if (!mk_n) break;
            float em = em_n;
            if (t < 511) {
                em_n = g_emis[(size_t)(t + 1) * 576 + b * 9 + j];
                mk_n = mask[b * 512 + t + 1];
            } else {
                mk_n = 0;
            }
            float ea = __expf(a);
            float s0 = 0.f, s1 = 0.f, s2 = 0.f;
            #pragma unroll
            for (int i = 0; i < 9; i += 3) {
                float e0 = __shfl_sync(0x1ffu, ea, i);
                float e1 = __shfl_sync(0x1ffu, ea, i + 1);
                float e2 = __shfl_sync(0x1ffu, ea, i + 2);
                s0 += e0 * E[i];
                s1 += e1 * E[i + 1];
                s2 += e2 * E[i + 2];
            }
            float u = __logf(s0 + s1 + s2) + em;
            float u0 = __shfl_sync(0x1ffu, u, 0);
            base += u0;
            a = u - u0;
        }
        float z = a + end_trans[j];
        float ez = __expf(z);
        float s = 0.f;
        #pragma unroll
        for (int i = 0; i < 9; i++) s += __shfl_sync(0x1ffu, ez, i);
        logZ = base + __logf(s);
    }
    if (lane == 0) g_llh[b] = score - logZ;
}

// ===========================================================================
// K5: final deterministic reduction  out = -mean(llh)
// ===========================================================================
__global__ void k_final(float* __restrict__ out)
{
    __shared__ float s[64];
    const int tid = threadIdx.x;
    s[tid] = g_llh[tid];
    __syncthreads();
    if (tid == 0) {
        float acc = 0.f;
        for (int i = 0; i < 64; i++) acc += s[i];
        out[0] = -acc / 64.f;
    }
}

// ===========================================================================
extern "C" void kernel_launch(void* const* d_in, const int* in_sizes, int n_in,
                              void* d_out, int out_size)
{
    const bool dictOrder = (in_sizes[2] == 15000000);
    const int ie = dictOrder ? 2 : 3;
    const int im = dictOrder ? 16 : 2;

    const int*   sent    = (const int*)  d_in[0];
    const int*   tags    = (const int*)  d_in[1];
    const float* embed   = (const float*)d_in[ie + 0];
    const float* wih_f   = (const float*)d_in[ie + 1];
    const float* whh_f   = (const float*)d_in[ie + 2];
    const float* bih_f   = (const float*)d_in[ie + 3];
    const float* bhh_f   = (const float*)d_in[ie + 4];
    const float* wih_b   = (const float*)d_in[ie + 5];
    const float* whh_b   = (const float*)d_in[ie + 6];
    const float* bih_b   = (const float*)d_in[ie + 7];
    const float* bhh_b   = (const float*)d_in[ie + 8];
    const float* w_out   = (const float*)d_in[ie + 9];
    const float* b_out   = (const float*)d_in[ie + 10];
    const float* s_tr    = (const float*)d_in[ie + 11];
    const float* e_tr    = (const float*)d_in[ie + 12];
    const float* trans   = (const float*)d_in[ie + 13];
    const int*   mask    = (const int*)  d_in[im];
    float*       out     = (float*)d_out;

    // shift the ncu -s/-c profiled slot onto k_rec
    k_pre1<<<1, 32>>>();
    k_pre2<<<1, 32>>>();

    dim3 g1(512, 32);
    k_inproj<<<g1, 256>>>(sent, embed, wih_f, wih_b, bih_f, bhh_f, bih_b, bhh_b);
    k_rec<<<128, 256>>>(whh_f, whh_b);
    k_emis<<<512, 256>>>(w_out, b_out);
    k_crf<<<64, 32>>>(tags, mask, s_tr, e_tr, trans);
    k_final<<<1, 64>>>(out);
}